// round 15
// baseline (speedup 1.0000x reference)
#include <cuda_runtime.h>
#include <cuda_fp16.h>
#include <cstdint>
typedef uint32_t u32;

#define XPP 648                       // half2 words per channel-pair plane (≡8 mod 32)
#define BW_OFF (14 * XPP)             // 9072
#define SMEM_WORDS (BW_OFF + 5760)    // B: [kh<9][n<8][tq<4] 20-word kw-paired slots
#define SMEM_BYTES (SMEM_WORDS * 4)   // 59328 B

__device__ __forceinline__ void mma16(float (&d)[4],
                                      u32 a0, u32 a1, u32 a2, u32 a3, u32 b0, u32 b1) {
    asm("mma.sync.aligned.m16n8k16.row.col.f32.f16.f16.f32 "
        "{%0,%1,%2,%3},{%4,%5,%6,%7},{%8,%9},{%0,%1,%2,%3};"
        : "+f"(d[0]), "+f"(d[1]), "+f"(d[2]), "+f"(d[3])
        : "r"(a0), "r"(a1), "r"(a2), "r"(a3), "r"(b0), "r"(b1));
}

__device__ __forceinline__ u32 h2(float a, float b) {
    __half2 v = __floats2half2_rn(a, b);      // .x = a (low half)
    return *reinterpret_cast<u32*>(&v);
}

// load one channel-pair plane window: d[j] = xs[(tq+2p)*XPP + row*40 + 2gq+16mt + j]
__device__ __forceinline__ void loadp(u32 (&d)[10], const u32* xrow, int p, int tq) {
    const u32* q = xrow + (tq + 2 * p) * XPP;
    #pragma unroll
    for (int i = 0; i < 5; ++i) {
        uint2 v = *(const uint2*)(q + 2 * i);
        d[2 * i] = v.x; d[2 * i + 1] = v.y;
    }
}

// 18-HMMA burst: jcLo over planes (A,B), jcHi over (B,C); B tile kw-paired uint4
__device__ __forceinline__ void burst(float (&aL)[4], float (&aH)[4],
                                      const u32 (&A)[10], const u32 (&B)[10],
                                      const u32 (&C)[10], const u32* bkh) {
    #pragma unroll
    for (int kwp = 0; kwp < 4; ++kwp) {
        uint4 bb = *(const uint4*)(bkh + 4 * kwp);
        const int k0 = 2 * kwp;
        mma16(aL, A[8 - k0], A[9 - k0], B[8 - k0], B[9 - k0], bb.x, bb.y);
        mma16(aH, B[8 - k0], B[9 - k0], C[8 - k0], C[9 - k0], bb.x, bb.y);
        mma16(aL, A[7 - k0], A[8 - k0], B[7 - k0], B[8 - k0], bb.z, bb.w);
        mma16(aH, B[7 - k0], B[8 - k0], C[7 - k0], C[8 - k0], bb.z, bb.w);
    }
    uint2 b8 = *(const uint2*)(bkh + 16);
    mma16(aL, A[0], A[1], B[0], B[1], b8.x, b8.y);
    mma16(aH, B[0], B[1], C[0], C[1], b8.x, b8.y);
}

// out[b, n*32+cc, h, w] = sum_{c<16,kh,kw} x[b,(4cc-c)&127,(h-kh)&31,(w-kw)&31] * W[n,c,kh,kw]
// CTA = (g, hq, b); warp = (hloc<8, mt<2). M-row r -> w = 2r / 2(r-8)+1.
// Planes P0..P5 (cp = tq+2p) roll through 4 register buffers, period-2 schedule:
// every plane load precedes a burst it does not feed -> loads overlap HMMAs.
__global__ __launch_bounds__(512, 2)
void fconv_mma(const float* __restrict__ x, const float* __restrict__ w,
               float* __restrict__ out)
{
    extern __shared__ u32 sm[];
    u32* xs = sm;                 // [cp<14][r<16][j<40] half2(x[2cp], x[2cp+1])
    u32* Bs = sm + BW_OFF;        // [((kh*8+n)*4+tq)*20 + 2*kw + u]

    const int t = threadIdx.x;
    const int g = blockIdx.x & 7, hq = blockIdx.x >> 3, b = blockIdx.y;
    const int chb = (16 * g + 113) & 127;          // (16g - 15) mod 128
    const float* xb = x + (size_t)b * 131072;

    // ---- stage x channel-pairs, rows 8hq-8 .. 8hq+7, halo'd cols of 40 ----
    for (int i = t; i < 8960; i += 512) {
        int cp = i / 640, r2 = i % 640, r = r2 / 40, j = r2 % 40;
        int h = (8 * hq - 8 + r) & 31, wc = (j + 24) & 31;
        float f0 = xb[((chb + 2 * cp)     & 127) * 1024 + h * 32 + wc];
        float f1 = xb[((chb + 2 * cp + 1) & 127) * 1024 + h * 32 + wc];
        xs[cp * XPP + r * 40 + j] = h2(f0, f1);
    }
    // ---- stage B kw-paired: slot (kh,n,tq2): word 2*kw+u = half2(W[n][c0],W[n][c0-1]),
    //      c0 = 15-(8u+2tq2); words 18,19 pad ----
    for (int i = t; i < 5760; i += 512) {
        int slot = i / 20, rem = i % 20, kw = rem >> 1, u = rem & 1;
        int kh = slot >> 5, n = (slot >> 2) & 7, tq2 = slot & 3;
        u32 val = 0;
        if (kw < 9) {
            int c0 = 15 - (8 * u + 2 * tq2);
            val = h2(w[n * 1296 + c0 * 81 + kh * 9 + kw],
                     w[n * 1296 + (c0 - 1) * 81 + kh * 9 + kw]);
        }
        Bs[i] = val;
    }
    __syncthreads();

    const int lane = t & 31, wid = t >> 5, gq = lane >> 2, tq = lane & 3;
    const int hloc = wid & 7, mt = wid >> 3;
    const int h = 8 * hq + hloc;

    float acc0[4] = {0,0,0,0}, acc1[4] = {0,0,0,0};
    float acc2[4] = {0,0,0,0}, acc3[4] = {0,0,0,0};
    u32 W[10], X[10], Y[10], Z[10];

    const u32* xr = xs + (hloc + 8) * 40 + 2 * gq + 16 * mt;   // row for kh, -40/kh
    const u32* bk = Bs + (gq * 4 + tq) * 20;                   // + kh*640

    // prologue: kh=0 grp0 planes
    loadp(W, xr, 0, tq); loadp(X, xr, 2, tq); loadp(Y, xr, 4, tq);

    #pragma unroll 1
    for (int khp = 0; khp < 4; ++khp) {
        // ---- even kh = 2*khp: entry (W,X,Y) = (P0,P2,P4) ----
        {
            const u32* bkh = bk + (2 * khp) * 640;
            const u32* xrn = xr - 40;
            loadp(Z, xr, 1, tq);
            burst(acc0, acc2, W, X, Y, bkh);
            loadp(W, xr, 3, tq); loadp(X, xr, 5, tq);
            loadp(Y, xrn, 0, tq);
            burst(acc1, acc3, Z, W, X, bkh);
            loadp(Z, xrn, 2, tq); loadp(W, xrn, 4, tq);
            xr = xrn;
        }
        // ---- odd kh = 2*khp+1: entry (Y,Z,W) = (P0,P2,P4) ----
        {
            const u32* bkh = bk + (2 * khp + 1) * 640;
            const u32* xrn = xr - 40;
            loadp(X, xr, 1, tq);
            burst(acc0, acc2, Y, Z, W, bkh);
            loadp(Y, xr, 3, tq); loadp(Z, xr, 5, tq);
            loadp(W, xrn, 0, tq);
            burst(acc1, acc3, X, Y, Z, bkh);
            loadp(X, xrn, 2, tq); loadp(Y, xrn, 4, tq);
            xr = xrn;
        }
    }
    // ---- kh = 8 (even roles, no next prefetch) ----
    {
        const u32* bkh = bk + 8 * 640;
        loadp(Z, xr, 1, tq);
        burst(acc0, acc2, W, X, Y, bkh);
        loadp(W, xr, 3, tq); loadp(X, xr, 5, tq);
        burst(acc1, acc3, Z, W, X, bkh);
    }

    // ---- store: rows (gq, gq+8) -> w = (2gq, 2gq+1) + 16mt; cols 2tq,2tq+1 ----
    const int w0 = 2 * gq + 16 * mt;
    float* ob = out + (size_t)b * 262144 + h * 32 + w0;
    #pragma unroll
    for (int jc = 0; jc < 4; ++jc) {
        const float* a = (jc == 0) ? acc0 : (jc == 1) ? acc1 : (jc == 2) ? acc2 : acc3;
        const int cc = 4 * g + jc;
        #pragma unroll
        for (int d = 0; d < 2; ++d) {
            const int ch = (2 * tq + d) * 32 + cc;
            *(float2*)(ob + (size_t)ch * 1024) = make_float2(a[d], a[2 + d]);
        }
    }
}

extern "C" void kernel_launch(void* const* d_in, const int* in_sizes, int n_in,
                              void* d_out, int out_size)
{
    const float* x = (const float*)d_in[0];   // (32,128,32,32) f32
    const float* w = (const float*)d_in[1];   // (8,16,9,9) f32
    float* out = (float*)d_out;               // (32,256,32,32) f32

    cudaFuncSetAttribute(fconv_mma,
                         cudaFuncAttributeMaxDynamicSharedMemorySize, SMEM_BYTES);
    dim3 grid(32, 32);                        // (g, hq) x b  -> 1024 CTAs
    fconv_mma<<<grid, 512, SMEM_BYTES>>>(x, w, out);
}

// round 16
// speedup vs baseline: 1.6448x; 1.6448x over previous
#include <cuda_runtime.h>
#include <cuda_fp16.h>
#include <cstdint>
typedef uint32_t u32;

#define XPP 648                       // half2 words per channel-pair plane (≡8 mod 32)
#define BW_OFF (14 * XPP)             // 9072
#define SMEM_WORDS (BW_OFF + 5760)    // B: [kh<9][n<8][tq<4] 20-word kw-paired slots
#define SMEM_BYTES (SMEM_WORDS * 4)   // 59328 B

__device__ u32 gB[5760];              // prebuilt fp16 B table (kw-paired)

__device__ __forceinline__ u32 h2(float a, float b) {
    __half2 v = __floats2half2_rn(a, b);      // .x = a (low half)
    return *reinterpret_cast<u32*>(&v);
}

// ---- prep: build B table once. slot (kh,n,tq2): word 2*kw+u =
//      half2(W[n][15-(8u+2tq2)], W[n][14-(8u+2tq2)]) at tap kh*9+kw ----
__global__ void prep_B(const float* __restrict__ w) {
    int i = blockIdx.x * 512 + threadIdx.x;
    if (i < 5760) {
        int slot = i / 20, rem = i % 20, kw = rem >> 1, u = rem & 1;
        int kh = slot >> 5, n = (slot >> 2) & 7, tq2 = slot & 3;
        u32 val = 0;
        if (kw < 9) {
            int c0 = 15 - (8 * u + 2 * tq2);
            val = h2(w[n * 1296 + c0 * 81 + kh * 9 + kw],
                     w[n * 1296 + (c0 - 1) * 81 + kh * 9 + kw]);
        }
        gB[i] = val;
    }
}

__device__ __forceinline__ void mma16(float (&d)[4],
                                      u32 a0, u32 a1, u32 a2, u32 a3, u32 b0, u32 b1) {
    asm("mma.sync.aligned.m16n8k16.row.col.f32.f16.f16.f32 "
        "{%0,%1,%2,%3},{%4,%5,%6,%7},{%8,%9},{%0,%1,%2,%3};"
        : "+f"(d[0]), "+f"(d[1]), "+f"(d[2]), "+f"(d[3])
        : "r"(a0), "r"(a1), "r"(a2), "r"(a3), "r"(b0), "r"(b1));
}

// 18-HMMA burst over planes (A,B) -> aL and (B,C) -> aH; B tile kw-paired uint4
__device__ __forceinline__ void burst(float (&aL)[4], float (&aH)[4],
                                      const u32 (&A)[10], const u32 (&B)[10],
                                      const u32 (&C)[10], const u32* bkh) {
    #pragma unroll
    for (int kwp = 0; kwp < 4; ++kwp) {
        uint4 bb = *(const uint4*)(bkh + 4 * kwp);
        const int k0 = 2 * kwp;
        mma16(aL, A[8 - k0], A[9 - k0], B[8 - k0], B[9 - k0], bb.x, bb.y);
        mma16(aH, B[8 - k0], B[9 - k0], C[8 - k0], C[9 - k0], bb.x, bb.y);
        mma16(aL, A[7 - k0], A[8 - k0], B[7 - k0], B[8 - k0], bb.z, bb.w);
        mma16(aH, B[7 - k0], B[8 - k0], C[7 - k0], C[8 - k0], bb.z, bb.w);
    }
    uint2 b8 = *(const uint2*)(bkh + 16);
    mma16(aL, A[0], A[1], B[0], B[1], b8.x, b8.y);
    mma16(aH, B[0], B[1], C[0], C[1], b8.x, b8.y);
}

// out[b, n*32+cc, h, w] = sum_{c<16,kh,kw} x[b,(4cc-c)&127,(h-kh)&31,(w-kw)&31] * W[n,c,kh,kw]
// CTA = (g, hq, b); warp = (hloc<8, mt<2). M-row r -> w = 2r / 2(r-8)+1.
// kh body: two jc-groups, 3 planes (30 regs) live -> fits 64-reg cap, no spills.
__global__ __launch_bounds__(512, 2)
void fconv_mma(const float* __restrict__ x, float* __restrict__ out)
{
    extern __shared__ u32 sm[];
    u32* xs = sm;                 // [cp<14][r<16][j<40] half2(x[2cp], x[2cp+1])
    u32* Bs = sm + BW_OFF;        // copy of gB

    const int t = threadIdx.x;
    const int g = blockIdx.x & 7, hq = blockIdx.x >> 3, b = blockIdx.y;
    const int chb = (16 * g + 113) & 127;          // (16g - 15) mod 128
    const float* xb = x + (size_t)b * 131072;

    // ---- stage B: plain vector copy of prebuilt table ----
    for (int i = t; i < 1440; i += 512)
        ((uint4*)Bs)[i] = ((const uint4*)gB)[i];

    // ---- stage x channel-pairs as float2 along w (even j0 never wraps) ----
    for (int i = t; i < 4480; i += 512) {
        int cp = i / 320, r2 = i % 320, r = r2 / 20, jp = r2 % 20;
        int h = (8 * hq - 8 + r) & 31, wc = (2 * jp + 24) & 31;
        float2 f0 = *(const float2*)(xb + ((chb + 2 * cp)     & 127) * 1024 + h * 32 + wc);
        float2 f1 = *(const float2*)(xb + ((chb + 2 * cp + 1) & 127) * 1024 + h * 32 + wc);
        *(uint2*)(xs + cp * XPP + r * 40 + 2 * jp) =
            make_uint2(h2(f0.x, f1.x), h2(f0.y, f1.y));
    }
    __syncthreads();

    const int lane = t & 31, wid = t >> 5, gq = lane >> 2, tq = lane & 3;
    const int hloc = wid & 7, mt = wid >> 3;
    const int h = 8 * hq + hloc;

    float acc[4][4];
    #pragma unroll
    for (int jc = 0; jc < 4; ++jc)
        #pragma unroll
        for (int q = 0; q < 4; ++q) acc[jc][q] = 0.f;

    #pragma unroll 1
    for (int kh = 0; kh < 9; ++kh) {
        const int rl = hloc + 8 - kh;                 // staged row 0..15
        const u32* xrow = xs + rl * 40 + 2 * gq + 16 * mt;
        const u32* bkh  = Bs + kh * 640 + gq * 80 + tq * 20;

        #pragma unroll
        for (int grp = 0; grp < 2; ++grp) {
            // planes grp, grp+2, grp+4 (channel-pair cp = tq + 2*plane)
            u32 CH[3][10];
            #pragma unroll
            for (int pl = 0; pl < 3; ++pl) {
                const u32* p = xrow + (tq + 2 * (grp + 2 * pl)) * XPP;
                #pragma unroll
                for (int q = 0; q < 5; ++q) {
                    uint2 v = *(const uint2*)(p + 2 * q);
                    CH[pl][2 * q] = v.x; CH[pl][2 * q + 1] = v.y;
                }
            }
            burst(acc[grp], acc[grp + 2], CH[0], CH[1], CH[2], bkh);
        }
    }

    // ---- store: rows (gq, gq+8) -> w = (2gq, 2gq+1) + 16mt; cols 2tq,2tq+1 ----
    const int w0 = 2 * gq + 16 * mt;
    float* ob = out + (size_t)b * 262144 + h * 32 + w0;
    #pragma unroll
    for (int jc = 0; jc < 4; ++jc) {
        const int cc = 4 * g + jc;
        #pragma unroll
        for (int d = 0; d < 2; ++d) {
            const int ch = (2 * tq + d) * 32 + cc;
            *(float2*)(ob + (size_t)ch * 1024) = make_float2(acc[jc][d], acc[jc][2 + d]);
        }
    }
}

extern "C" void kernel_launch(void* const* d_in, const int* in_sizes, int n_in,
                              void* d_out, int out_size)
{
    const float* x = (const float*)d_in[0];   // (32,128,32,32) f32
    const float* w = (const float*)d_in[1];   // (8,16,9,9) f32
    float* out = (float*)d_out;               // (32,256,32,32) f32

    prep_B<<<12, 512>>>(w);
    cudaFuncSetAttribute(fconv_mma,
                         cudaFuncAttributeMaxDynamicSharedMemorySize, SMEM_BYTES);
    dim3 grid(32, 32);                        // (g, hq) x b  -> 1024 CTAs
    fconv_mma<<<grid, 512, SMEM_BYTES>>>(x, out);
}

// round 17
// speedup vs baseline: 1.7126x; 1.0413x over previous
#include <cuda_runtime.h>
#include <cuda_fp16.h>
#include <cstdint>
typedef uint32_t u32;

#define XPP 648                       // half2 words per channel-pair plane (≡8 mod 32)
#define BW_OFF (14 * XPP)             // 9072
#define SMEM_WORDS (BW_OFF + 5760)    // B: [kh<9][n<8][tq<4] 20-word kw-paired slots
#define SMEM_BYTES (SMEM_WORDS * 4)   // 59328 B

__device__ u32 gB[5760];              // prebuilt fp16 B table (kw-paired)

__device__ __forceinline__ u32 h2(float a, float b) {
    __half2 v = __floats2half2_rn(a, b);      // .x = a (low half)
    return *reinterpret_cast<u32*>(&v);
}

// ---- prep: build B table once. slot (kh,n,tq2): word 2*kw+u =
//      half2(W[n][15-(8u+2tq2)], W[n][14-(8u+2tq2)]) at tap kh*9+kw ----
__global__ void prep_B(const float* __restrict__ w) {
    int i = blockIdx.x * 512 + threadIdx.x;
    if (i < 5760) {
        int slot = i / 20, rem = i % 20, kw = rem >> 1, u = rem & 1;
        int kh = slot >> 5, n = (slot >> 2) & 7, tq2 = slot & 3;
        u32 val = 0;
        if (kw < 9) {
            int c0 = 15 - (8 * u + 2 * tq2);
            val = h2(w[n * 1296 + c0 * 81 + kh * 9 + kw],
                     w[n * 1296 + (c0 - 1) * 81 + kh * 9 + kw]);
        }
        gB[i] = val;
    }
}

__device__ __forceinline__ void mma16(float (&d)[4],
                                      u32 a0, u32 a1, u32 a2, u32 a3, u32 b0, u32 b1) {
    asm("mma.sync.aligned.m16n8k16.row.col.f32.f16.f16.f32 "
        "{%0,%1,%2,%3},{%4,%5,%6,%7},{%8,%9},{%0,%1,%2,%3};"
        : "+f"(d[0]), "+f"(d[1]), "+f"(d[2]), "+f"(d[3])
        : "r"(a0), "r"(a1), "r"(a2), "r"(a3), "r"(b0), "r"(b1));
}

// 18-HMMA burst over planes (A,B) -> aL and (B,C) -> aH; B tile kw-paired uint4
__device__ __forceinline__ void burst(float (&aL)[4], float (&aH)[4],
                                      const u32 (&A)[10], const u32 (&B)[10],
                                      const u32 (&C)[10], const u32* bkh) {
    #pragma unroll
    for (int kwp = 0; kwp < 4; ++kwp) {
        uint4 bb = *(const uint4*)(bkh + 4 * kwp);
        const int k0 = 2 * kwp;
        mma16(aL, A[8 - k0], A[9 - k0], B[8 - k0], B[9 - k0], bb.x, bb.y);
        mma16(aH, B[8 - k0], B[9 - k0], C[8 - k0], C[9 - k0], bb.x, bb.y);
        mma16(aL, A[7 - k0], A[8 - k0], B[7 - k0], B[8 - k0], bb.z, bb.w);
        mma16(aH, B[7 - k0], B[8 - k0], C[7 - k0], C[8 - k0], bb.z, bb.w);
    }
    uint2 b8 = *(const uint2*)(bkh + 16);
    mma16(aL, A[0], A[1], B[0], B[1], b8.x, b8.y);
    mma16(aH, B[0], B[1], C[0], C[1], b8.x, b8.y);
}

// out[b, n*32+cc, h, w] = sum_{c<16,kh,kw} x[b,(4cc-c)&127,(h-kh)&31,(w-kw)&31] * W[n,c,kh,kw]
// CTA = (g, hq, b); warp = (hloc<8, mt<2). M-row r -> w = 2r / 2(r-8)+1.
// kh body: two jc-groups, 3 planes (30 regs) live -> fits 64-reg cap, no spills.
__global__ __launch_bounds__(512, 2)
void fconv_mma(const float* __restrict__ x, float* __restrict__ out)
{
    extern __shared__ u32 sm[];
    u32* xs = sm;                 // [cp<14][r<16][j<40] half2(x[2cp], x[2cp+1])
    u32* Bs = sm + BW_OFF;        // copy of gB

    const int t = threadIdx.x;
    const int g = blockIdx.x & 7, hq = blockIdx.x >> 3, b = blockIdx.y;
    const int chb = (16 * g + 113) & 127;          // (16g - 15) mod 128
    const float* xb = x + (size_t)b * 131072;

    // ---- stage B: plain vector copy of prebuilt table ----
    for (int i = t; i < 1440; i += 512)
        ((uint4*)Bs)[i] = ((const uint4*)gB)[i];

    // ---- stage x channel-pairs, float4 quads along w (wc ≡ 0 mod 4, no wrap) ----
    for (int i = t; i < 2240; i += 512) {
        int cp = i / 160, r2 = i % 160, r = r2 / 10, jq = r2 % 10;
        int h = (8 * hq - 8 + r) & 31, wc = (4 * jq + 24) & 31;
        float4 f0 = *(const float4*)(xb + ((chb + 2 * cp)     & 127) * 1024 + h * 32 + wc);
        float4 f1 = *(const float4*)(xb + ((chb + 2 * cp + 1) & 127) * 1024 + h * 32 + wc);
        *(uint4*)(xs + cp * XPP + r * 40 + 4 * jq) =
            make_uint4(h2(f0.x, f1.x), h2(f0.y, f1.y), h2(f0.z, f1.z), h2(f0.w, f1.w));
    }
    __syncthreads();

    const int lane = t & 31, wid = t >> 5, gq = lane >> 2, tq = lane & 3;
    const int hloc = wid & 7, mt = wid >> 3;
    const int h = 8 * hq + hloc;

    float acc[4][4];
    #pragma unroll
    for (int jc = 0; jc < 4; ++jc)
        #pragma unroll
        for (int q = 0; q < 4; ++q) acc[jc][q] = 0.f;

    #pragma unroll 1
    for (int kh = 0; kh < 9; ++kh) {
        const int rl = hloc + 8 - kh;                 // staged row 0..15
        const u32* xrow = xs + rl * 40 + 2 * gq + 16 * mt;
        const u32* bkh  = Bs + kh * 640 + gq * 80 + tq * 20;

        #pragma unroll
        for (int grp = 0; grp < 2; ++grp) {
            // planes grp, grp+2, grp+4 (channel-pair cp = tq + 2*plane)
            u32 CH[3][10];
            #pragma unroll
            for (int pl = 0; pl < 3; ++pl) {
                const u32* p = xrow + (tq + 2 * (grp + 2 * pl)) * XPP;
                #pragma unroll
                for (int q = 0; q < 5; ++q) {
                    uint2 v = *(const uint2*)(p + 2 * q);
                    CH[pl][2 * q] = v.x; CH[pl][2 * q + 1] = v.y;
                }
            }
            burst(acc[grp], acc[grp + 2], CH[0], CH[1], CH[2], bkh);
        }
    }

    // ---- store: rows (gq, gq+8) -> w = (2gq, 2gq+1) + 16mt; cols 2tq,2tq+1 ----
    const int w0 = 2 * gq + 16 * mt;
    float* ob = out + (size_t)b * 262144 + h * 32 + w0;
    #pragma unroll
    for (int jc = 0; jc < 4; ++jc) {
        const int cc = 4 * g + jc;
        #pragma unroll
        for (int d = 0; d < 2; ++d) {
            const int ch = (2 * tq + d) * 32 + cc;
            *(float2*)(ob + (size_t)ch * 1024) = make_float2(acc[jc][d], acc[jc][2 + d]);
        }
    }
}

extern "C" void kernel_launch(void* const* d_in, const int* in_sizes, int n_in,
                              void* d_out, int out_size)
{
    const float* x = (const float*)d_in[0];   // (32,128,32,32) f32
    const float* w = (const float*)d_in[1];   // (8,16,9,9) f32
    float* out = (float*)d_out;               // (32,256,32,32) f32

    prep_B<<<12, 512>>>(w);
    cudaFuncSetAttribute(fconv_mma,
                         cudaFuncAttributeMaxDynamicSharedMemorySize, SMEM_BYTES);
    dim3 grid(32, 32);                        // (g, hq) x b  -> 1024 CTAs
    fconv_mma<<<grid, 512, SMEM_BYTES>>>(x, out);
}